// round 1
// baseline (speedup 1.0000x reference)
#include <cuda_runtime.h>

// Problem constants (fixed by dataset: B=2, N=512, E=128, H=8, D=16)
#define B_    2
#define N_    512
#define E_    128
#define H_    8
#define D_    16
#define ROWS_ (B_ * N_)   // 1024

// Scratch (device globals: allocation-free rule)
__device__ float g_q[ROWS_ * E_];    // q * (1/sqrt(D)), layout [row][h*16+d]
__device__ float g_v[ROWS_ * E_];    // v, same layout
__device__ float g_hat[ROWS_ * E_]; // attention output pre-projection

// ---------------------------------------------------------------------------
// Kernel 1: q/v projection.  qkv = x @ w_qkv^T ; keep only cols [0,128) (q)
// and [256,384) (v). k is skipped entirely: the q.k term is constant over m
// and cancels in softmax. 1/sqrt(D)=0.25 folded into q.
// Grid: ROWS_/16 CTAs, 16 rows each; 256 threads.
// ---------------------------------------------------------------------------
__global__ __launch_bounds__(256) void qv_kernel(const float* __restrict__ x,
                                                 const float* __restrict__ w_qkv) {
    __shared__ float x_s[16][128];   // 8 KB
    __shared__ float w_t[128][65];   // 33 KB, transposed, padded (bank-safe)

    const int row0 = blockIdx.x * 16;
    const int tid  = threadIdx.x;

    for (int idx = tid; idx < 16 * 128; idx += 256)
        x_s[idx >> 7][idx & 127] = x[(row0 + (idx >> 7)) * 128 + (idx & 127)];

    // 4 subtiles of 64 output cols: q[0:64], q[64:128], v[0:64], v[64:128]
    for (int st = 0; st < 4; st++) {
        const int wbase = (st < 2) ? st * 64 : 256 + (st - 2) * 64;
        __syncthreads();   // protects x_s (st=0) and w_t reuse (st>0)
        for (int idx = tid; idx < 64 * 128; idx += 256) {
            int c = idx >> 7, j = idx & 127;
            w_t[j][c] = w_qkv[(wbase + c) * 128 + j];  // coalesced read
        }
        __syncthreads();

        const int c  = tid & 63;
        const int rg = tid >> 6;           // 4 row-groups of 4 rows
        float acc[4] = {0.f, 0.f, 0.f, 0.f};
        #pragma unroll 8
        for (int j = 0; j < 128; j++) {
            float w = w_t[j][c];           // stride-1 across lanes: conflict-free
            #pragma unroll
            for (int rr = 0; rr < 4; rr++)
                acc[rr] = fmaf(w, x_s[rg * 4 + rr][j], acc[rr]);  // broadcast
        }
        const float scale = (st < 2) ? 0.25f : 1.0f;
        float* dst = (st < 2) ? g_q : g_v;
        const int cg = (st & 1) * 64 + c;
        #pragma unroll
        for (int rr = 0; rr < 4; rr++)
            dst[(row0 + rg * 4 + rr) * 128 + cg] = acc[rr] * scale;
    }
}

// ---------------------------------------------------------------------------
// Kernel 2 (hot): edge-conditioned attention, one CTA per (b,n) row,
// one warp per head, 16 m-values per lane, everything in registers.
//   s[h,m]  = sum_d q'[h,d] * lrelu(e_m * wk[h,d] + bk[h,d])      (q' = q/4)
//   p       = softmax_m(s)    (unnormalized; 1/Z folded at the end)
//   hat[h,d]= v[h,d] + (sum_m p~[m] * lrelu(e_m * wv[h,d]+bv[h,d])) / Z
// lrelu(x) = fmaxf(x, 0.01x). Inner loops: 3 fma-pipe + 1 alu op / element.
// ---------------------------------------------------------------------------
__global__ __launch_bounds__(256) void attn_kernel(const float* __restrict__ e,
                                                   const float* __restrict__ w_ekv,
                                                   const float* __restrict__ b_ekv) {
    __shared__ float e_s[N_];
    __shared__ float q_s[128], v_s[128];
    __shared__ float wk_s[128], bk_s[128], wv_s[128], bv_s[128];

    const int row  = blockIdx.x;     // b*N + n
    const int tid  = threadIdx.x;
    const int lane = tid & 31;
    const int h    = tid >> 5;       // warp == head

    for (int idx = tid; idx < N_; idx += 256) e_s[idx] = e[row * N_ + idx];
    if (tid < 128) {
        q_s[tid]  = g_q[row * 128 + tid];
        v_s[tid]  = g_v[row * 128 + tid];
        wk_s[tid] = w_ekv[tid];          // w_ekv[:,0], first HD = K weights
        bk_s[tid] = b_ekv[tid];
    } else {
        int t = tid - 128;
        wv_s[t] = w_ekv[128 + t];        // second HD = V weights
        bv_s[t] = b_ekv[128 + t];
    }
    __syncthreads();

    // ---- phase 1: scores (register-resident per-head params) ----
    float qd[16], wk[16], bk[16];
    #pragma unroll
    for (int d = 0; d < 16; d++) {
        qd[d] = q_s[h * 16 + d];
        wk[d] = wk_s[h * 16 + d];
        bk[d] = bk_s[h * 16 + d];
    }
    float ev[16], s[16];
    #pragma unroll
    for (int i = 0; i < 16; i++) {
        const float em = e_s[i * 32 + lane];   // conflict-free
        ev[i] = em;
        float acc = 0.f;
        #pragma unroll
        for (int d = 0; d < 16; d++) {
            float t = fmaf(em, wk[d], bk[d]);
            float l = fmaxf(t, 0.01f * t);     // leaky_relu
            acc = fmaf(qd[d], l, acc);
        }
        s[i] = acc;
    }

    // ---- softmax over m (512 values live in this warp's registers) ----
    float mx = s[0];
    #pragma unroll
    for (int i = 1; i < 16; i++) mx = fmaxf(mx, s[i]);
    #pragma unroll
    for (int k = 16; k >= 1; k >>= 1) mx = fmaxf(mx, __shfl_xor_sync(0xffffffffu, mx, k));
    float Z = 0.f;
    #pragma unroll
    for (int i = 0; i < 16; i++) { s[i] = __expf(s[i] - mx); Z += s[i]; }
    #pragma unroll
    for (int k = 16; k >= 1; k >>= 1) Z += __shfl_xor_sync(0xffffffffu, Z, k);
    const float invZ = 1.f / Z;

    // ---- phase 2: V accumulation ----
    float wv[16], bv[16], acc[16];
    #pragma unroll
    for (int d = 0; d < 16; d++) {
        wv[d]  = wv_s[h * 16 + d];
        bv[d]  = bv_s[h * 16 + d];
        acc[d] = 0.f;
    }
    #pragma unroll
    for (int i = 0; i < 16; i++) {
        const float em = ev[i];
        const float p  = s[i];   // unnormalized prob
        #pragma unroll
        for (int d = 0; d < 16; d++) {
            float t = fmaf(em, wv[d], bv[d]);
            float l = fmaxf(t, 0.01f * t);
            acc[d] = fmaf(p, l, acc[d]);
        }
    }

    // ---- warp all-reduce over m; lane d keeps total for dim d ----
    float res = 0.f;
    #pragma unroll
    for (int d = 0; d < 16; d++) {
        float v = acc[d];
        #pragma unroll
        for (int k = 16; k >= 1; k >>= 1) v += __shfl_xor_sync(0xffffffffu, v, k);
        if (lane == d) res = v;
    }
    if (lane < 16)
        g_hat[row * 128 + h * 16 + lane] = v_s[h * 16 + lane] + res * invZ;
}

// ---------------------------------------------------------------------------
// Kernel 3: output projection  out = hat @ w_prj^T + b_prj
// Same tiling as kernel 1.
// ---------------------------------------------------------------------------
__global__ __launch_bounds__(256) void proj_kernel(const float* __restrict__ w_prj,
                                                   const float* __restrict__ b_prj,
                                                   float* __restrict__ out) {
    __shared__ float h_s[16][128];
    __shared__ float w_t[128][65];

    const int row0 = blockIdx.x * 16;
    const int tid  = threadIdx.x;

    for (int idx = tid; idx < 16 * 128; idx += 256)
        h_s[idx >> 7][idx & 127] = g_hat[(row0 + (idx >> 7)) * 128 + (idx & 127)];

    for (int st = 0; st < 2; st++) {
        __syncthreads();
        for (int idx = tid; idx < 64 * 128; idx += 256) {
            int c = idx >> 7, j = idx & 127;
            w_t[j][c] = w_prj[(st * 64 + c) * 128 + j];
        }
        __syncthreads();

        const int c  = tid & 63;
        const int rg = tid >> 6;
        float acc[4] = {0.f, 0.f, 0.f, 0.f};
        #pragma unroll 8
        for (int j = 0; j < 128; j++) {
            float w = w_t[j][c];
            #pragma unroll
            for (int rr = 0; rr < 4; rr++)
                acc[rr] = fmaf(w, h_s[rg * 4 + rr][j], acc[rr]);
        }
        const int cg = st * 64 + c;
        const float bias = b_prj[cg];
        #pragma unroll
        for (int rr = 0; rr < 4; rr++)
            out[(row0 + rg * 4 + rr) * 128 + cg] = acc[rr] + bias;
    }
}

// ---------------------------------------------------------------------------
extern "C" void kernel_launch(void* const* d_in, const int* in_sizes, int n_in,
                              void* d_out, int out_size) {
    const float* x     = (const float*)d_in[0];
    const float* e     = (const float*)d_in[1];
    const float* w_qkv = (const float*)d_in[2];
    const float* w_ekv = (const float*)d_in[3];
    const float* b_ekv = (const float*)d_in[4];
    const float* w_prj = (const float*)d_in[5];
    const float* b_prj = (const float*)d_in[6];
    float* out = (float*)d_out;

    qv_kernel  <<<ROWS_ / 16, 256>>>(x, w_qkv);
    attn_kernel<<<ROWS_,      256>>>(e, w_ekv, b_ekv);
    proj_kernel<<<ROWS_ / 16, 256>>>(w_prj, b_prj, out);
}

// round 2
// speedup vs baseline: 1.5567x; 1.5567x over previous
#include <cuda_runtime.h>

// Problem constants (fixed by dataset: B=2, N=512, E=128, H=8, D=16)
#define B_    2
#define N_    512
#define E_    128
#define H_    8
#define D_    16
#define ROWS_ (B_ * N_)   // 1024

// Scratch (device globals: allocation-free rule)
__device__ float g_q[ROWS_ * E_];    // q * (1/sqrt(D)), layout [row][h*16+d]
__device__ float g_v[ROWS_ * E_];    // v, same layout
__device__ float g_hat[ROWS_ * E_];  // attention output pre-projection

// ---------------- packed fp32x2 helpers (Blackwell FFMA2) -------------------
typedef unsigned long long u64;
#define ABS2_MASK 0x7fffffff7fffffffULL

__device__ __forceinline__ u64 pack2(float lo, float hi) {
    u64 r; asm("mov.b64 %0, {%1, %2};" : "=l"(r) : "f"(lo), "f"(hi)); return r;
}
__device__ __forceinline__ float2 unpk2(u64 v) {
    float2 f; asm("mov.b64 {%0, %1}, %2;" : "=f"(f.x), "=f"(f.y) : "l"(v)); return f;
}
__device__ __forceinline__ u64 ffma2(u64 a, u64 b, u64 c) {
    u64 d; asm("fma.rn.f32x2 %0, %1, %2, %3;" : "=l"(d) : "l"(a), "l"(b), "l"(c)); return d;
}

// ---------------------------------------------------------------------------
// GEMM kernels: C[32r x 64c] tile = X[32 x 128] @ W[64 x 128]^T per CTA.
// w_s transposed to [j][c] with pad 68 so reads are conflict-free LDS.128.
// 256 threads: tx = tid%16 -> 4 cols, ty = tid/16 -> rows {ty, ty+16}.
// Dynamic smem: x_s[32][128] (16KB) + w_s[128][68] (34KB) = 51200 B.
// ---------------------------------------------------------------------------
#define GEMM_SMEM_BYTES (32 * 128 * 4 + 128 * 68 * 4)

__device__ __forceinline__ void gemm_fill(const float* __restrict__ src_rows,
                                          const float* __restrict__ w_rows,
                                          float (*x_s)[128], float (*w_s)[68],
                                          int tid) {
    // x: 32x128 floats = 1024 float4, coalesced, conflict-free flat stores
    const float4* x4 = (const float4*)src_rows;
    float4* xs4 = (float4*)x_s;
    #pragma unroll
    for (int i = 0; i < 4; i++) {
        int idx = tid + i * 256;
        xs4[idx] = x4[idx];
    }
    // w: 64 rows x 128, scalar coalesced loads; stores j*68+c -> 4-way max
    #pragma unroll
    for (int i = 0; i < 32; i++) {
        int idx = tid + i * 256;          // 0..8191
        int j = idx & 127, c = idx >> 7;  // lane varies j -> coalesced gmem
        w_s[j][c] = w_rows[c * 128 + j];
    }
}

__device__ __forceinline__ void gemm_compute(const float (*x_s)[128],
                                             const float (*w_s)[68],
                                             int tx, int ty,
                                             float acc0[4], float acc1[4]) {
    #pragma unroll
    for (int jb = 0; jb < 32; jb++) {
        float4 xa4 = *(const float4*)&x_s[ty][jb * 4];
        float4 xb4 = *(const float4*)&x_s[ty + 16][jb * 4];
        float xa[4] = {xa4.x, xa4.y, xa4.z, xa4.w};
        float xb[4] = {xb4.x, xb4.y, xb4.z, xb4.w};
        #pragma unroll
        for (int k = 0; k < 4; k++) {
            float4 wv = *(const float4*)&w_s[jb * 4 + k][tx * 4];
            acc0[0] = fmaf(xa[k], wv.x, acc0[0]);
            acc0[1] = fmaf(xa[k], wv.y, acc0[1]);
            acc0[2] = fmaf(xa[k], wv.z, acc0[2]);
            acc0[3] = fmaf(xa[k], wv.w, acc0[3]);
            acc1[0] = fmaf(xb[k], wv.x, acc1[0]);
            acc1[1] = fmaf(xb[k], wv.y, acc1[1]);
            acc1[2] = fmaf(xb[k], wv.z, acc1[2]);
            acc1[3] = fmaf(xb[k], wv.w, acc1[3]);
        }
    }
}

// qv: out cols 0..255 of qkv; st=0,1 -> q (scaled 0.25), st=2,3 -> v
__global__ __launch_bounds__(256) void qv_kernel(const float* __restrict__ x,
                                                 const float* __restrict__ w_qkv) {
    extern __shared__ float sm[];
    float (*x_s)[128] = (float(*)[128])sm;
    float (*w_s)[68]  = (float(*)[68])(sm + 32 * 128);

    const int tid  = threadIdx.x;
    const int row0 = blockIdx.y * 32;
    const int st   = blockIdx.x;
    const int wbase = (st < 2) ? st * 64 : 128 + st * 64;  // 0,64,256,320

    gemm_fill(x + row0 * 128, w_qkv + wbase * 128, x_s, w_s, tid);
    __syncthreads();

    const int tx = tid & 15, ty = tid >> 4;
    float acc0[4] = {0, 0, 0, 0}, acc1[4] = {0, 0, 0, 0};
    gemm_compute(x_s, w_s, tx, ty, acc0, acc1);

    const float scale = (st < 2) ? 0.25f : 1.0f;
    float* dst = (st < 2) ? g_q : g_v;
    const int cg = (st & 1) * 64 + tx * 4;
    float4 o0 = {acc0[0] * scale, acc0[1] * scale, acc0[2] * scale, acc0[3] * scale};
    float4 o1 = {acc1[0] * scale, acc1[1] * scale, acc1[2] * scale, acc1[3] * scale};
    *(float4*)&dst[(row0 + ty) * 128 + cg]      = o0;
    *(float4*)&dst[(row0 + ty + 16) * 128 + cg] = o1;
}

// proj: out = g_hat @ w_prj^T + b_prj
__global__ __launch_bounds__(256) void proj_kernel(const float* __restrict__ w_prj,
                                                   const float* __restrict__ b_prj,
                                                   float* __restrict__ out) {
    extern __shared__ float sm[];
    float (*x_s)[128] = (float(*)[128])sm;
    float (*w_s)[68]  = (float(*)[68])(sm + 32 * 128);

    const int tid  = threadIdx.x;
    const int row0 = blockIdx.y * 32;
    const int wbase = blockIdx.x * 64;

    gemm_fill(g_hat + row0 * 128, w_prj + wbase * 128, x_s, w_s, tid);
    __syncthreads();

    const int tx = tid & 15, ty = tid >> 4;
    float acc0[4] = {0, 0, 0, 0}, acc1[4] = {0, 0, 0, 0};
    gemm_compute(x_s, w_s, tx, ty, acc0, acc1);

    const int cg = wbase + tx * 4;
    float4 bv = *(const float4*)&b_prj[cg];
    float4 o0 = {acc0[0] + bv.x, acc0[1] + bv.y, acc0[2] + bv.z, acc0[3] + bv.w};
    float4 o1 = {acc1[0] + bv.x, acc1[1] + bv.y, acc1[2] + bv.z, acc1[3] + bv.w};
    *(float4*)&out[(row0 + ty) * 128 + cg]      = o0;
    *(float4*)&out[(row0 + ty + 16) * 128 + cg] = o1;
}

// ---------------------------------------------------------------------------
// Kernel 2 (hot): edge-conditioned attention, one CTA per (b,n), one warp per
// head, 16 m per lane, packed f32x2 over d-pairs.
//   lrelu(t) = 0.505*t + 0.495*|t|  ->  q*lrelu(t) = (0.505q)*t + (0.495q)*|t|
// Per packed (i,dd): FFMA2(t) + AND + 2x FFMA2(acc) = 1.5 fma-slots/element.
// ---------------------------------------------------------------------------
__global__ __launch_bounds__(256) void attn_kernel(const float* __restrict__ e,
                                                   const float* __restrict__ w_ekv,
                                                   const float* __restrict__ b_ekv) {
    __shared__ float e_s[N_];
    __shared__ float q_s[128], v_s[128];
    __shared__ float wk_s[128], bk_s[128], wv_s[128], bv_s[128];

    const int row  = blockIdx.x;     // b*N + n
    const int tid  = threadIdx.x;
    const int lane = tid & 31;
    const int h    = tid >> 5;       // warp == head

    for (int idx = tid; idx < N_; idx += 256) e_s[idx] = e[row * N_ + idx];
    if (tid < 128) {
        q_s[tid]  = g_q[row * 128 + tid];
        v_s[tid]  = g_v[row * 128 + tid];
        wk_s[tid] = w_ekv[tid];
        bk_s[tid] = b_ekv[tid];
    } else {
        int t = tid - 128;
        wv_s[t] = w_ekv[128 + t];
        bv_s[t] = b_ekv[128 + t];
    }
    __syncthreads();

    // ---- phase 1: scores ----
    u64 wk2[8], bk2[8], qa2[8], qb2[8];
    #pragma unroll
    for (int dd = 0; dd < 8; dd++) {
        float2 w = ((const float2*)wk_s)[h * 8 + dd];
        float2 b = ((const float2*)bk_s)[h * 8 + dd];
        float2 q = ((const float2*)q_s)[h * 8 + dd];
        wk2[dd] = pack2(w.x, w.y);
        bk2[dd] = pack2(b.x, b.y);
        qa2[dd] = pack2(0.505f * q.x, 0.505f * q.y);
        qb2[dd] = pack2(0.495f * q.x, 0.495f * q.y);
    }
    float ev[16], s[16];
    #pragma unroll
    for (int i = 0; i < 16; i++) {
        const float em = e_s[i * 32 + lane];
        ev[i] = em;
        const u64 em2 = pack2(em, em);
        u64 acc2 = 0ULL;  // (+0.f, +0.f)
        #pragma unroll
        for (int dd = 0; dd < 8; dd++) {
            u64 t2 = ffma2(em2, wk2[dd], bk2[dd]);
            u64 a2 = t2 & ABS2_MASK;            // |t| per half (alu pipe)
            acc2 = ffma2(qa2[dd], t2, acc2);
            acc2 = ffma2(qb2[dd], a2, acc2);
        }
        float2 f = unpk2(acc2);
        s[i] = f.x + f.y;
    }

    // ---- softmax over m (512 values live in this warp's registers) ----
    float mx = s[0];
    #pragma unroll
    for (int i = 1; i < 16; i++) mx = fmaxf(mx, s[i]);
    #pragma unroll
    for (int k = 16; k >= 1; k >>= 1) mx = fmaxf(mx, __shfl_xor_sync(0xffffffffu, mx, k));
    float Z = 0.f;
    #pragma unroll
    for (int i = 0; i < 16; i++) { s[i] = __expf(s[i] - mx); Z += s[i]; }
    #pragma unroll
    for (int k = 16; k >= 1; k >>= 1) Z += __shfl_xor_sync(0xffffffffu, Z, k);
    const float invZ = 1.f / Z;

    // ---- phase 2: V accumulation ----
    // hat_d = 0.505 * sum_m p*t + 0.495 * sum_m p*|t|
    u64 wv2[8], bv2[8], A2[8], B2[8];
    #pragma unroll
    for (int dd = 0; dd < 8; dd++) {
        float2 w = ((const float2*)wv_s)[h * 8 + dd];
        float2 b = ((const float2*)bv_s)[h * 8 + dd];
        wv2[dd] = pack2(w.x, w.y);
        bv2[dd] = pack2(b.x, b.y);
        A2[dd] = 0ULL;
        B2[dd] = 0ULL;
    }
    #pragma unroll
    for (int i = 0; i < 16; i++) {
        const u64 em2 = pack2(ev[i], ev[i]);
        const u64 p2  = pack2(s[i], s[i]);
        #pragma unroll
        for (int dd = 0; dd < 8; dd++) {
            u64 t2 = ffma2(em2, wv2[dd], bv2[dd]);
            u64 a2 = t2 & ABS2_MASK;
            A2[dd] = ffma2(p2, t2, A2[dd]);
            B2[dd] = ffma2(p2, a2, B2[dd]);
        }
    }
    float acc[16];
    #pragma unroll
    for (int dd = 0; dd < 8; dd++) {
        float2 fa = unpk2(A2[dd]);
        float2 fb = unpk2(B2[dd]);
        acc[2 * dd]     = 0.505f * fa.x + 0.495f * fb.x;
        acc[2 * dd + 1] = 0.505f * fa.y + 0.495f * fb.y;
    }

    // ---- warp all-reduce over m; lane d keeps total for dim d ----
    float res = 0.f;
    #pragma unroll
    for (int d = 0; d < 16; d++) {
        float v = acc[d];
        #pragma unroll
        for (int k = 16; k >= 1; k >>= 1) v += __shfl_xor_sync(0xffffffffu, v, k);
        if (lane == d) res = v;
    }
    if (lane < 16)
        g_hat[row * 128 + h * 16 + lane] = v_s[h * 16 + lane] + res * invZ;
}

// ---------------------------------------------------------------------------
extern "C" void kernel_launch(void* const* d_in, const int* in_sizes, int n_in,
                              void* d_out, int out_size) {
    const float* x     = (const float*)d_in[0];
    const float* e     = (const float*)d_in[1];
    const float* w_qkv = (const float*)d_in[2];
    const float* w_ekv = (const float*)d_in[3];
    const float* b_ekv = (const float*)d_in[4];
    const float* w_prj = (const float*)d_in[5];
    const float* b_prj = (const float*)d_in[6];
    float* out = (float*)d_out;

    cudaFuncSetAttribute((const void*)qv_kernel,
                         cudaFuncAttributeMaxDynamicSharedMemorySize, GEMM_SMEM_BYTES);
    cudaFuncSetAttribute((const void*)proj_kernel,
                         cudaFuncAttributeMaxDynamicSharedMemorySize, GEMM_SMEM_BYTES);

    qv_kernel  <<<dim3(4, 32), 256, GEMM_SMEM_BYTES>>>(x, w_qkv);
    attn_kernel<<<ROWS_,       256>>>(e, w_ekv, b_ekv);
    proj_kernel<<<dim3(2, 32), 256, GEMM_SMEM_BYTES>>>(w_prj, b_prj, out);
}